// round 15
// baseline (speedup 1.0000x reference)
#include <cuda_runtime.h>

// Blocks_86096914416144 — SNN block scan, R15: warp-specialized producer/
// consumer. CTA=256: threads 0-127 = consumers (R5 math body BYTE-IDENTICAL,
// x from SMEM, spikes to SMEM); threads 128-255 = producers (all GMEM traffic:
// LDG x 3 blocks ahead -> STS ring, LDS spikes -> STG 1 block behind).
// One __syncthreads per block-iteration; x ring depth 4, spike ring depth 2
// (>=1 barrier between every produce/consume of a slot).
// Rationale (R5-R14): stall-integral bound at 2 warps/SMSP; producers add
// eligible warps that absorb ALL memory stalls without duplicating math or
// putting shuffles on the carry chain. FP ops untouched -> rel_err 0.0.

#define T_LEN   1024
#define TB      8
#define NBLK    (T_LEN / TB)      // 128
#define BATCH   32
#define NOUT    1024
#define BN      (BATCH * NOUT)    // 32768
#define LPC     128               // lanes per CTA
#define CTA     256               // 128 consumers + 128 producers

__global__ __launch_bounds__(CTA)
void blocks_snn_kernel(const float* __restrict__ x,
                       const float* __restrict__ beta_raw,
                       const float* __restrict__ p_raw,
                       const float* __restrict__ b_raw,
                       float* __restrict__ out)
{
    __shared__ float xs[4][TB][LPC];   // x ring, 16KB
    __shared__ float ss[2][TB][LPC];   // spike ring, 4KB

    const int lt   = threadIdx.x & (LPC - 1);
    const int lane = blockIdx.x * LPC + lt;

    if (threadIdx.x >= LPC) {
        // ================= PRODUCER =================
        const float* xp = x + lane;
        float*       op = out + lane;
        float pr[2][TB];                       // LDG landing ring

        // prologue: blocks 0,1 -> smem; block 2 -> regs (STS'd at iter 0)
        #pragma unroll
        for (int t = 0; t < TB; t++) xs[0][t][lt] = xp[(size_t)t * BN];
        #pragma unroll
        for (int t = 0; t < TB; t++) xs[1][t][lt] = xp[(size_t)(TB + t) * BN];
        #pragma unroll
        for (int t = 0; t < TB; t++) pr[0][t] = xp[(size_t)(2 * TB + t) * BN];
        __syncthreads();                       // sync #0 (matches consumer)

        #pragma unroll 1
        for (int g = 0; g < NBLK / 4; g++) {
            #pragma unroll
            for (int u = 0; u < 4; u++) {
                const int i = 4 * g + u;

                // STS block i+2 (loaded last iter) into slot (i+2)&3
                if (i + 2 < NBLK) {
                    #pragma unroll
                    for (int t = 0; t < TB; t++)
                        xs[(u + 2) & 3][t][lt] = pr[u & 1][t];
                }
                // LDG block i+3 into the other reg ring half
                if (i + 3 < NBLK) {
                    const float* xb = xp + (size_t)(i + 3) * TB * BN;
                    #pragma unroll
                    for (int t = 0; t < TB; t++)
                        pr[(u + 1) & 1][t] = xb[t * BN];
                }
                // STG spikes of block i-1 (written by consumers at iter i-1)
                if (i > 0) {
                    float* ob = op + (size_t)(i - 1) * TB * BN;
                    #pragma unroll
                    for (int t = 0; t < TB; t++)
                        ob[t * BN] = ss[(u + 1) & 1][t][lt];   // (i-1)&1
                }
                __syncthreads();
            }
        }
        // epilogue: STG block 127 (written at iter 127, barrier passed)
        {
            float* ob = op + (size_t)(NBLK - 1) * TB * BN;
            #pragma unroll
            for (int t = 0; t < TB; t++)
                ob[t * BN] = ss[1][t][lt];                     // 127&1
        }
    } else {
        // ================= CONSUMER (R5 body byte-for-byte) =================
        const int n = lane & (NOUT - 1);

        const float beta  = fminf(fmaxf(beta_raw[n], 0.001f), 0.999f);
        const float p     = fminf(fmaxf(fabsf(p_raw[n]), 0.0f), 0.999f);
        const float bb    = fminf(fmaxf(fabsf(b_raw[n]), 0.001f), 1.0f);
        const float inv_p = 1.0f / p;

        float bpow[TB];
        bpow[0] = 1.0f;
        #pragma unroll
        for (int k = 1; k < TB; k++) bpow[k] = powf(beta, (float)k);

        float ppow[TB + 1];
        ppow[0] = 1.0f;
        #pragma unroll
        for (int k = 1; k <= TB; k++) ppow[k] = powf(p, (float)k);

        float z[TB];
        #pragma unroll
        for (int t = 0; t < TB; t++) z[t] = 0.0f;
        float a    = 0.0f;
        float vmem = 0.0f;

        __syncthreads();                       // sync #0: blocks 0,1 visible

        float creg[2][TB];                     // LDS landing ring
        #pragma unroll
        for (int t = 0; t < TB; t++) creg[0][t] = xs[0][t][lt];

        #pragma unroll 1
        for (int g = 0; g < NBLK / 4; g++) {
            #pragma unroll
            for (int u = 0; u < 4; u++) {
                const int i = 4 * g + u;

                // prefetch block i+1 from slot (i+1)&3 (STS'd >=1 barrier ago)
                if (i + 1 < NBLK) {
                    #pragma unroll
                    for (int t = 0; t < TB; t++)
                        creg[(u + 1) & 1][t] = xs[(u + 1) & 3][t][lt];
                }
                const float* xc = creg[u & 1];

                // ---- head: sg, maskf, ds from z (exact R5) ----
                float sg[TB];
                float maskf = 0.0f;
                #pragma unroll
                for (int t = 0; t < TB; t++) {
                    sg[t] = (z[t] == 1.0f) ? 1.0f : 0.0f;
                    if (sg[t] != 0.0f) maskf = 1.0f;
                }

                float a_at = 0.0f;
                #pragma unroll
                for (int t = 0; t < TB; t++)
                    if (sg[t] != 0.0f) a_at += ppow[t + 1] * a;
                a_at += inv_p;

                int ds = 0;
                #pragma unroll
                for (int t = 0; t < TB; t++)
                    if (z[t] > 1.0f) ds++;

                float pds = ppow[0];
                #pragma unroll
                for (int k = 1; k <= TB; k++)
                    if (ds == k) pds = ppow[k];

                const float new_a = a_at * pds;
                a = (maskf != 0.0f) ? new_a : (ppow[TB] * a);

                // ---- refractory masking + carry-in (exact R5) ----
                const float v_init = vmem * (1.0f - maskf);
                float cur[TB];
                #pragma unroll
                for (int t = 0; t < TB; t++)
                    cur[t] = (z[t] < maskf) ? 0.0f : xc[t];
                cur[0] = cur[0] + beta * v_init;

                // ---- causal decayed sum + threshold (exact R5) ----
                float f[TB];
                float mlast = 0.0f;
                #pragma unroll
                for (int t = 0; t < TB; t++) {
                    float m = 0.0f;
                    #pragma unroll
                    for (int s = 0; s <= t; s++)
                        m += bpow[t - s] * cur[s];
                    const float vth = 1.0f + bb * (ppow[t + 1] * a);
                    f[t] = ((m - vth) > 0.0f) ? 1.0f : 0.0f;
                    if (t == TB - 1) mlast = m;
                }

                // ---- z = double cumsum; spikes -> SMEM (exact values) ----
                float c = 0.0f, zr = 0.0f;
                #pragma unroll
                for (int t = 0; t < TB; t++) {
                    c  += f[t];
                    zr += c;
                    z[t] = zr;
                    ss[u & 1][t][lt] = (zr == 1.0f) ? 1.0f : 0.0f;
                }

                vmem = mlast;
                __syncthreads();
            }
        }
    }
}

extern "C" void kernel_launch(void* const* d_in, const int* in_sizes, int n_in,
                              void* d_out, int out_size)
{
    const float* x        = (const float*)d_in[0];
    const float* beta_raw = (const float*)d_in[1];
    const float* p_raw    = (const float*)d_in[2];
    const float* b_raw    = (const float*)d_in[3];
    float* out = (float*)d_out;

    blocks_snn_kernel<<<BN / LPC, CTA>>>(x, beta_raw, p_raw, b_raw, out);
}

// round 16
// speedup vs baseline: 1.1727x; 1.1727x over previous
#include <cuda_runtime.h>

// Blocks_86096914416144 — SNN block scan, R16: R13 body BYTE-IDENTICAL
// (bit-exact numerics, 57.8us champion class) with ONE change: the per-
// iteration prefetch guard `if (blk+3 < NBLK)` is replaced by an
// UNCONDITIONAL prefetch of min(blk+3, 127). Ring-slot audit: block 127 is
// loaded at blk=124 into slot 3 and consumed at blk=127; the clamped tail
// re-reads (blk=125,126,127 -> slots 0,1,2) land in already-consumed slots
// and are never read. Removes all hot-loop branches (ptxas emits BSSY/BSYNC,
// 33-56 cyc, for C++ if{} per SASS_QUICKREF) at the cost of 24 L2-hit loads
// per thread across the whole kernel.

#define T_LEN   1024
#define TB      8
#define NBLK    (T_LEN / TB)      // 128
#define BATCH   32
#define NOUT    1024
#define BN      (BATCH * NOUT)    // 32768
#define CTA     128

__global__ __launch_bounds__(CTA)
void blocks_snn_kernel(const float* __restrict__ x,
                       const float* __restrict__ beta_raw,
                       const float* __restrict__ p_raw,
                       const float* __restrict__ b_raw,
                       float* __restrict__ out)
{
    const int tid = blockIdx.x * CTA + threadIdx.x;   // 0..32767
    const int n   = tid & (NOUT - 1);

    const float beta  = fminf(fmaxf(beta_raw[n], 0.001f), 0.999f);
    const float p     = fminf(fmaxf(fabsf(p_raw[n]), 0.0f), 0.999f);
    const float bb    = fminf(fmaxf(fabsf(b_raw[n]), 0.001f), 1.0f);
    const float inv_p = 1.0f / p;

    float bpow[TB];
    bpow[0] = 1.0f;
    #pragma unroll
    for (int k = 1; k < TB; k++) bpow[k] = powf(beta, (float)k);

    float ppow[TB + 1];
    ppow[0] = 1.0f;
    #pragma unroll
    for (int k = 1; k <= TB; k++) ppow[k] = powf(p, (float)k);

    // carry state (exact R5/R13)
    float z[TB];
    #pragma unroll
    for (int t = 0; t < TB; t++) z[t] = 0.0f;
    float a    = 0.0f;
    float vmem = 0.0f;

    const float* xp = x + tid;
    float*       op = out + tid;

    // 4-slot register ring, prefetch 3 blocks ahead (exact R5/R13)
    float buf[4][TB];
    #pragma unroll
    for (int pb = 0; pb < 3; pb++) {
        const float* xb = xp + (size_t)pb * TB * BN;
        #pragma unroll
        for (int t = 0; t < TB; t++) buf[pb][t] = xb[t * BN];
    }

    #pragma unroll 1
    for (int g = 0; g < NBLK / 4; g++) {
        #pragma unroll
        for (int u = 0; u < 4; u++) {
            const int blk = 4 * g + u;

            // ---- UNCONDITIONAL clamped prefetch (no branch in hot loop) ----
            {
                const int pfb = (blk + 3 < NBLK - 1) ? (blk + 3) : (NBLK - 1);
                const float* xb = xp + (size_t)pfb * TB * BN;
                #pragma unroll
                for (int t = 0; t < TB; t++)
                    buf[(u + 3) & 3][t] = xb[t * BN];
            }
            const float* xc = buf[u & 3];

            // ---- head: sg, maskf, ds from z (exact R5) ----
            float sg[TB];
            float maskf = 0.0f;
            #pragma unroll
            for (int t = 0; t < TB; t++) {
                sg[t] = (z[t] == 1.0f) ? 1.0f : 0.0f;
                if (sg[t] != 0.0f) maskf = 1.0f;
            }

            float a_at = 0.0f;
            #pragma unroll
            for (int t = 0; t < TB; t++)
                if (sg[t] != 0.0f) a_at += ppow[t + 1] * a;
            a_at += inv_p;

            int ds = 0;
            #pragma unroll
            for (int t = 0; t < TB; t++)
                if (z[t] > 1.0f) ds++;

            float pds = ppow[0];
            #pragma unroll
            for (int k = 1; k <= TB; k++)
                if (ds == k) pds = ppow[k];

            const float new_a = a_at * pds;
            a = (maskf != 0.0f) ? new_a : (ppow[TB] * a);

            // ---- refractory masking + carry-in (exact R5) ----
            const float v_init = vmem * (1.0f - maskf);
            float cur[TB];
            #pragma unroll
            for (int t = 0; t < TB; t++)
                cur[t] = (z[t] < maskf) ? 0.0f : xc[t];
            cur[0] = cur[0] + beta * v_init;

            // ---- causal decayed sums, s-major (bit-identical per-t order) ----
            float m[TB];
            #pragma unroll
            for (int t = 0; t < TB; t++) m[t] = 0.0f;
            #pragma unroll
            for (int s = 0; s < TB; s++) {
                #pragma unroll
                for (int t = s; t < TB; t++)
                    m[t] += bpow[t - s] * cur[s];
            }

            // ---- threshold (exact R5) ----
            float f[TB];
            #pragma unroll
            for (int t = 0; t < TB; t++) {
                const float vth = 1.0f + bb * (ppow[t + 1] * a);
                f[t] = ((m[t] - vth) > 0.0f) ? 1.0f : 0.0f;
            }
            const float mlast = m[TB - 1];

            // ---- z = double cumsum; emit spikes (exact R5) ----
            float* ob = op + (size_t)blk * TB * BN;
            float c = 0.0f, zr = 0.0f;
            #pragma unroll
            for (int t = 0; t < TB; t++) {
                c  += f[t];
                zr += c;
                z[t] = zr;
                ob[t * BN] = (zr == 1.0f) ? 1.0f : 0.0f;
            }

            vmem = mlast;
        }
    }
}

extern "C" void kernel_launch(void* const* d_in, const int* in_sizes, int n_in,
                              void* d_out, int out_size)
{
    const float* x        = (const float*)d_in[0];
    const float* beta_raw = (const float*)d_in[1];
    const float* p_raw    = (const float*)d_in[2];
    const float* b_raw    = (const float*)d_in[3];
    float* out = (float*)d_out;

    blocks_snn_kernel<<<BN / CTA, CTA>>>(x, beta_raw, p_raw, b_raw, out);
}

// round 17
// speedup vs baseline: 1.3953x; 1.1898x over previous
#include <cuda_runtime.h>

// Blocks_86096914416144 — SNN block scan, FINAL (revert to R5 champion).
// One thread per (b,n) lane; carry = z[8] + scalar a + scalar vmem;
// 4-slot register ring prefetching 3 blocks ahead; CTA=128.
// Proven: 57.8us, rel_err 0.0. Eleven structural variants (R6-R16) all
// regressed or were neutral: the kernel is stall-integral-bound on 32768
// mandatory-serial scan chains at 1.73 warps/SMSP, and every attempt to add
// ILP/warps/width cost more in chain depth, duplication, or sync than it won.

#define T_LEN   1024
#define TB      8
#define NBLK    (T_LEN / TB)      // 128
#define BATCH   32
#define NOUT    1024
#define BN      (BATCH * NOUT)    // 32768
#define CTA     128

struct LaneState {
    float z[TB];
    float a;
    float vmem;
};

__device__ __forceinline__
void step_block(LaneState& st,
                const float* __restrict__ xc,
                float* __restrict__ ob,
                float beta, float bb, float inv_p,
                const float* __restrict__ bpow,
                const float* __restrict__ ppow)
{
    // sg (prev spikes) and maskf
    float sg[TB];
    float maskf = 0.0f;
    #pragma unroll
    for (int t = 0; t < TB; t++) {
        sg[t] = (st.z[t] == 1.0f) ? 1.0f : 0.0f;
        if (sg[t] != 0.0f) maskf = 1.0f;
    }

    // adaptation: a_at_spike = sum_t p^(t+1)*a*sg[t] + 1/p
    float a_at = 0.0f;
    #pragma unroll
    for (int t = 0; t < TB; t++)
        if (sg[t] != 0.0f) a_at += ppow[t + 1] * st.a;
    a_at += inv_p;

    int ds = 0;                         // decay_steps = count(z > 1)
    #pragma unroll
    for (int t = 0; t < TB; t++)
        if (st.z[t] > 1.0f) ds++;

    float pds = ppow[0];
    #pragma unroll
    for (int k = 1; k <= TB; k++)
        if (ds == k) pds = ppow[k];

    const float new_a = a_at * pds;
    st.a = (maskf != 0.0f) ? new_a : (ppow[TB] * st.a);

    // refractory masking + membrane carry-in
    const float v_init = st.vmem * (1.0f - maskf);
    float cur[TB];
    #pragma unroll
    for (int t = 0; t < TB; t++)
        cur[t] = (st.z[t] < maskf) ? 0.0f : xc[t];
    cur[0] = cur[0] + beta * v_init;

    // causal decayed sum + threshold
    float f[TB];
    float mlast = 0.0f;
    #pragma unroll
    for (int t = 0; t < TB; t++) {
        float m = 0.0f;
        #pragma unroll
        for (int s = 0; s <= t; s++)
            m += bpow[t - s] * cur[s];
        const float vth = 1.0f + bb * (ppow[t + 1] * st.a);
        f[t] = ((m - vth) > 0.0f) ? 1.0f : 0.0f;
        if (t == TB - 1) mlast = m;
    }

    // z = double cumsum of f; emit spikes (z == 1)
    float c = 0.0f, zr = 0.0f;
    #pragma unroll
    for (int t = 0; t < TB; t++) {
        c  += f[t];
        zr += c;
        st.z[t] = zr;
        ob[t * BN] = (zr == 1.0f) ? 1.0f : 0.0f;
    }

    st.vmem = mlast;
}

__global__ __launch_bounds__(CTA)
void blocks_snn_kernel(const float* __restrict__ x,
                       const float* __restrict__ beta_raw,
                       const float* __restrict__ p_raw,
                       const float* __restrict__ b_raw,
                       float* __restrict__ out)
{
    const int tid = blockIdx.x * CTA + threadIdx.x;   // 0..32767
    const int n   = tid & (NOUT - 1);

    const float beta  = fminf(fmaxf(beta_raw[n], 0.001f), 0.999f);
    const float p     = fminf(fmaxf(fabsf(p_raw[n]), 0.0f), 0.999f);
    const float bb    = fminf(fmaxf(fabsf(b_raw[n]), 0.001f), 1.0f);
    const float inv_p = 1.0f / p;

    float bpow[TB];
    bpow[0] = 1.0f;
    #pragma unroll
    for (int k = 1; k < TB; k++) bpow[k] = powf(beta, (float)k);

    float ppow[TB + 1];
    ppow[0] = 1.0f;
    #pragma unroll
    for (int k = 1; k <= TB; k++) ppow[k] = powf(p, (float)k);

    LaneState st;
    #pragma unroll
    for (int t = 0; t < TB; t++) st.z[t] = 0.0f;
    st.a = 0.0f;
    st.vmem = 0.0f;

    const float* xp = x + tid;
    float*       op = out + tid;

    // 4-slot register ring, prefetch 3 blocks ahead
    float buf[4][TB];
    #pragma unroll
    for (int pb = 0; pb < 3; pb++) {
        const float* xb = xp + (size_t)pb * TB * BN;
        #pragma unroll
        for (int t = 0; t < TB; t++) buf[pb][t] = xb[t * BN];
    }

    #pragma unroll 1
    for (int g = 0; g < NBLK / 4; g++) {
        #pragma unroll
        for (int u = 0; u < 4; u++) {
            const int blk = 4 * g + u;
            if (blk + 3 < NBLK) {
                const float* xb = xp + (size_t)(blk + 3) * TB * BN;
                #pragma unroll
                for (int t = 0; t < TB; t++)
                    buf[(u + 3) & 3][t] = xb[t * BN];
            }
            step_block(st, buf[u & 3], op + (size_t)blk * TB * BN,
                       beta, bb, inv_p, bpow, ppow);
        }
    }
}

extern "C" void kernel_launch(void* const* d_in, const int* in_sizes, int n_in,
                              void* d_out, int out_size)
{
    const float* x        = (const float*)d_in[0];
    const float* beta_raw = (const float*)d_in[1];
    const float* p_raw    = (const float*)d_in[2];
    const float* b_raw    = (const float*)d_in[3];
    float* out = (float*)d_out;

    blocks_snn_kernel<<<BN / CTA, CTA>>>(x, beta_raw, p_raw, b_raw, out);
}